// round 15
// baseline (speedup 1.0000x reference)
#include <cuda_runtime.h>
#include <cuda_bf16.h>
#include <cstdint>

#define Nn 19
#define GH 64
#define GE 64
#define Bb 256
#define Tt 256
#define BT (Bb*Tt)
#define LH 64
#define G4 256  // 4*LH

typedef unsigned long long ull;

// Scratch (device globals; no allocation allowed)
__device__ float g_emb[(size_t)BT * GE];     // (B*T, 64)
__device__ float g_xg0[(size_t)BT * G4];     // (B*T, 256)

// ---- packed f32x2 helpers -------------------------------------------------
__device__ __forceinline__ ull pk2(float lo, float hi) {
    ull r; asm("mov.b64 %0, {%1, %2};" : "=l"(r) : "f"(lo), "f"(hi)); return r;
}
__device__ __forceinline__ void upk2(ull v, float& lo, float& hi) {
    asm("mov.b64 {%0, %1}, %2;" : "=f"(lo), "=f"(hi) : "l"(v));
}
__device__ __forceinline__ ull fma2_(ull a, ull b, ull c) {
    ull d; asm("fma.rn.f32x2 %0, %1, %2, %3;" : "=l"(d) : "l"(a), "l"(b), "l"(c));
    return d;
}

// ---- fast transcendentals via MUFU tanh -----------------------------------
__device__ __forceinline__ float tanh_ap(float x) {
    float y; asm("tanh.approx.f32 %0, %1;" : "=f"(y) : "f"(x)); return y;
}
__device__ __forceinline__ float sigmoidf_(float x) {
    return fmaf(0.5f, tanh_ap(0.5f * x), 0.5f);
}

// ---------------------------------------------------------------------------
// Kernel 1: graph encoder with the An@A refactor:
//   X1 = relu( (An@A) @ W1^T + rs·b1^T ),  rs = An@1 (from dis, free)
// eliminating the separate H1 + An@H1 passes (760 -> ~615 FFMA2/graph).
// Structure otherwise = R11: 2-warp CTA, shared w1/w2 smem, f32x2 node
// packing (rows padded 19->20), ulonglong2 operand loads.
// M = An@A computed by lanes 0..18 (lane = column k of M), stored over AsT.
// ---------------------------------------------------------------------------
__global__ __launch_bounds__(64, 5)
void encoder_kernel(const float* __restrict__ conn, const int* __restrict__ mask,
                    const float* __restrict__ w1_w, const float* __restrict__ w1_b,
                    const float* __restrict__ w2_w, const float* __restrict__ w2_b)
{
    __shared__ __align__(16) float2 w2s2[GE][32];   // {w2[j][f], w2[j+32][f]}
    __shared__ __align__(16) float2 w1s2[Nn][32];   // {w1[j][k], w1[j+32][k]}
    __shared__ __align__(16) float AsT[2][Nn][20];  // [warp][k][i] = A[i][k]; becomes M^T
    __shared__ __align__(16) float AnT[2][Nn][20];  // [warp][k][i] = An[i][k]
    __shared__ __align__(16) float X1T[2][GE][20];
    __shared__ float dis[2][20];
    __shared__ __align__(8) float rss[2][20];       // rs[i] = sum_k An[i][k]

    const int tid = threadIdx.x;
    const int w = tid >> 5;      // warp in CTA
    const int t = tid & 31;      // lane

    for (int idx = tid; idx < GE * 32; idx += 64) {
        int f = idx >> 5, j = idx & 31;
        w2s2[f][j] = make_float2(w2_w[j * GE + f], w2_w[(j + 32) * GE + f]);
    }
    for (int idx = tid; idx < Nn * 32; idx += 64) {
        int k = idx >> 5, j = idx & 31;
        w1s2[k][j] = make_float2(w1_w[j * Nn + k], w1_w[(j + 32) * Nn + k]);
    }
    if (t < Nn) AnT[w][t][19] = 0.f;   // pad lane (never rewritten)
    if (t == 0) rss[w][19] = 0.f;      // pad -> X1T[.][19] = relu(0) = 0

    const float b1a_ = w1_b[t], b1b_ = w1_b[t + 32];
    const ull b1a = pk2(b1a_, b1a_), b1b = pk2(b1b_, b1b_);
    const float b2a_ = w2_b[t], b2b_ = w2_b[t + 32];
    const ull b2a = pk2(b2a_, b2a_), b2b = pk2(b2b_, b2b_);
    __syncthreads();

    for (int bt = blockIdx.x * 2 + w; bt < BT; bt += gridDim.x * 2) {
        // ---- load A transposed ----
        const float* A = conn + (size_t)bt * (Nn * Nn);
#pragma unroll
        for (int u = 0; u < 12; u++) {
            int idx = t + u * 32;
            if (idx < Nn * Nn) { int i = idx / Nn, k = idx - i * Nn; AsT[w][k][i] = A[idx]; }
        }
        __syncwarp();
        // ---- degree normalization factors ----
        if (t < Nn) {
            float d = 1.f;
#pragma unroll
            for (int k = 0; k < Nn; k++) d += AsT[w][k][t];
            dis[w][t] = rsqrtf(fmaxf(d, 1e-6f));
        }
        __syncwarp();
        // ---- build An (separate buffer; raw A still needed for M) ----
#pragma unroll
        for (int u = 0; u < 12; u++) {
            int idx = t + u * 32;
            if (idx < Nn * Nn) {
                int i = idx / Nn, k = idx - i * Nn;
                float a = AsT[w][k][i] + (i == k ? 1.f : 0.f);
                AnT[w][k][i] = a * dis[w][i] * dis[w][k];
            }
        }
        __syncwarp();

        // ---- rs[i] = sum_k An[i][k] = dis[i]*(sum_k A[i][k]*dis[k] + dis[i]) ----
        if (t < Nn) {
            float s = dis[w][t];
#pragma unroll
            for (int k = 0; k < Nn; k++) s = fmaf(AsT[w][k][t], dis[w][k], s);
            rss[w][t] = s * dis[w][t];
        }
        __syncwarp();

        // ---- M = An@A: lane l owns column k=l of M (all i, packed) ----
        // M[i][l] = sum_m An[i][m] * A[m][l];  A[m][l] = AsT[l][m]
        ull aA[10], aB[10];
        {
            float Arow[Nn];
            if (t < Nn) {
#pragma unroll
                for (int m = 0; m < Nn; m++) Arow[m] = AsT[w][t][m];
            } else {
#pragma unroll
                for (int m = 0; m < Nn; m++) Arow[m] = 0.f;
            }
#pragma unroll
            for (int ip = 0; ip < 10; ip++) aA[ip] = 0ull;
#pragma unroll
            for (int m = 0; m < Nn; m++) {
                const ull ad = pk2(Arow[m], Arow[m]);
                const ulonglong2* row = (const ulonglong2*)AnT[w][m];
#pragma unroll
                for (int q = 0; q < 5; q++) {
                    ulonglong2 r = row[q];
                    aA[2*q]   = fma2_(r.x, ad, aA[2*q]);
                    aA[2*q+1] = fma2_(r.y, ad, aA[2*q+1]);
                }
            }
            __syncwarp();   // all lanes done reading raw AsT
            // store M^T over AsT: lane l writes row AsT[l][i] = M[i][l]
            if (t < Nn) {
#pragma unroll
                for (int ip = 0; ip < 10; ip++) {
                    float lo, hi; upk2(aA[ip], lo, hi);
                    *(float2*)&AsT[w][t][2*ip] = make_float2(lo, hi);
                }
            }
            __syncwarp();
        }

        // ---- X1 = relu(M @ W1^T + rs·b1) -> smem transposed ----
        ull rsp[10];
#pragma unroll
        for (int ip = 0; ip < 10; ip++) rsp[ip] = *(const ull*)&rss[w][2*ip];
#pragma unroll
        for (int ip = 0; ip < 10; ip++) { aA[ip] = 0ull; aB[ip] = 0ull; }
#pragma unroll
        for (int k = 0; k < Nn; k++) {
            float2 wv = w1s2[k][t];
            const ull wA = pk2(wv.x, wv.x), wB = pk2(wv.y, wv.y);
            const ulonglong2* row = (const ulonglong2*)AsT[w][k];   // = M^T rows
#pragma unroll
            for (int q = 0; q < 5; q++) {
                ulonglong2 r = row[q];
                aA[2*q]   = fma2_(r.x, wA, aA[2*q]);
                aA[2*q+1] = fma2_(r.y, wA, aA[2*q+1]);
                aB[2*q]   = fma2_(r.x, wB, aB[2*q]);
                aB[2*q+1] = fma2_(r.y, wB, aB[2*q+1]);
            }
        }
#pragma unroll
        for (int ip = 0; ip < 10; ip++) {
            aA[ip] = fma2_(rsp[ip], b1a, aA[ip]);
            aB[ip] = fma2_(rsp[ip], b1b, aB[ip]);
        }
#pragma unroll
        for (int ip = 0; ip < 10; ip++) {
            float lo, hi;
            upk2(aA[ip], lo, hi);
            { float2 s; s.x = fmaxf(lo, 0.f); s.y = fmaxf(hi, 0.f); *(float2*)&X1T[w][t][2*ip] = s; }
            upk2(aB[ip], lo, hi);
            { float2 s; s.x = fmaxf(lo, 0.f); s.y = fmaxf(hi, 0.f); *(float2*)&X1T[w][t + 32][2*ip] = s; }
        }
        __syncwarp();

        // ---- H2 = X1@W2^T + b2 (w2 via one LDS.64 per f) ----
#pragma unroll
        for (int ip = 0; ip < 10; ip++) { aA[ip] = b2a; aB[ip] = b2b; }
#pragma unroll 8
        for (int f = 0; f < GE; f++) {
            float2 wv = w2s2[f][t];
            const ull wA = pk2(wv.x, wv.x), wB = pk2(wv.y, wv.y);
            const ulonglong2* row = (const ulonglong2*)X1T[w][f];
#pragma unroll
            for (int q = 0; q < 5; q++) {
                ulonglong2 r = row[q];
                aA[2*q]   = fma2_(r.x, wA, aA[2*q]);
                aA[2*q+1] = fma2_(r.y, wA, aA[2*q+1]);
                aB[2*q]   = fma2_(r.x, wB, aB[2*q]);
                aB[2*q+1] = fma2_(r.y, wB, aB[2*q+1]);
            }
        }
        float HsA[20], HsB[20];
#pragma unroll
        for (int ip = 0; ip < 10; ip++) { upk2(aA[ip], HsA[2*ip], HsA[2*ip+1]); upk2(aB[ip], HsB[2*ip], HsB[2*ip+1]); }

        // ---- X2 = relu(An @ H2); mean over nodes; mask ----
#pragma unroll
        for (int ip = 0; ip < 10; ip++) { aA[ip] = 0ull; aB[ip] = 0ull; }
#pragma unroll
        for (int k = 0; k < Nn; k++) {
            const ulonglong2* row = (const ulonglong2*)AnT[w][k];
            const ull hA = pk2(HsA[k], HsA[k]), hB = pk2(HsB[k], HsB[k]);
#pragma unroll
            for (int q = 0; q < 5; q++) {
                ulonglong2 r = row[q];
                aA[2*q]   = fma2_(r.x, hA, aA[2*q]);
                aA[2*q+1] = fma2_(r.y, hA, aA[2*q+1]);
                aB[2*q]   = fma2_(r.x, hB, aB[2*q]);
                aB[2*q+1] = fma2_(r.y, hB, aB[2*q+1]);
            }
        }
        float sA = 0.f, sB = 0.f;
#pragma unroll
        for (int ip = 0; ip < 10; ip++) {
            float lo, hi;
            upk2(aA[ip], lo, hi); sA += fmaxf(lo, 0.f) + fmaxf(hi, 0.f);
            upk2(aB[ip], lo, hi); sB += fmaxf(lo, 0.f) + fmaxf(hi, 0.f);
        }
        const float mf = (float)mask[bt] * (1.f / 19.f);
        g_emb[(size_t)bt * GE + t]      = sA * mf;
        g_emb[(size_t)bt * GE + t + 32] = sB * mf;
        __syncwarp();
    }
}

// ---------------------------------------------------------------------------
// Kernel 2: xg0 = emb @ Wih0^T + (bih0+bhh0); ulonglong2 operand loads.
// launch_bounds(128,3): reg cap 170 (est ~150) -> 3 CTAs/SM.
// ---------------------------------------------------------------------------
__global__ __launch_bounds__(128, 3)
void xg_kernel(const float* __restrict__ Wih0, const float* __restrict__ bih0,
               const float* __restrict__ bhh0)
{
    __shared__ __align__(16) float es[64 * GE];
    const int t = threadIdx.x;
    ull wp1[GE / 2], wp2[GE / 2];
#pragma unroll
    for (int k2 = 0; k2 < GE / 2; k2++)
        wp1[k2] = pk2(Wih0[t * GE + 2*k2], Wih0[t * GE + 2*k2 + 1]);
#pragma unroll
    for (int k2 = 0; k2 < GE / 2; k2++)
        wp2[k2] = pk2(Wih0[(t + 128) * GE + 2*k2], Wih0[(t + 128) * GE + 2*k2 + 1]);
    const float bias1 = bih0[t] + bhh0[t];
    const float bias2 = bih0[t + 128] + bhh0[t + 128];

    const float* ep = g_emb + (size_t)blockIdx.x * 64 * GE;
    for (int idx = t; idx < 64 * GE; idx += 128) es[idx] = ep[idx];
    __syncthreads();

    float* op = g_xg0 + (size_t)blockIdx.x * 64 * G4;
    for (int r = 0; r < 64; r++) {
        ull a1 = pk2(bias1, 0.f), a2 = pk2(bias2, 0.f);
        const ulonglong2* row = (const ulonglong2*)&es[r * GE];
#pragma unroll
        for (int q = 0; q < 16; q++) {
            ulonglong2 e = row[q];
            a1 = fma2_(e.x, wp1[2*q],     a1);
            a1 = fma2_(e.y, wp1[2*q + 1], a1);
            a2 = fma2_(e.x, wp2[2*q],     a2);
            a2 = fma2_(e.y, wp2[2*q + 1], a2);
        }
        float lo, hi;
        upk2(a1, lo, hi); op[r * G4 + t]       = lo + hi;
        upk2(a2, lo, hi); op[r * G4 + t + 128] = lo + hi;
    }
}

// ---------------------------------------------------------------------------
// Kernel 3: fused 2-layer LSTM + FC head — exact R11 proven version
// (384 threads, 3-group pipeline, MUFU tanh.approx, single accumulators).
// ---------------------------------------------------------------------------
__global__ __launch_bounds__(384, 1)
void lstm_kernel(const int* __restrict__ mask,
                 const float* __restrict__ Whh0,
                 const float* __restrict__ Wih1, const float* __restrict__ Whh1,
                 const float* __restrict__ bih1, const float* __restrict__ bhh1,
                 const float* __restrict__ fc1_w, const float* __restrict__ fc1_b,
                 const float* __restrict__ fc2_w, const float* __restrict__ fc2_b,
                 float* __restrict__ out)
{
    __shared__ __align__(16) float h0s[2][LH];
    __shared__ __align__(16) float h1s[2][LH];
    __shared__ float c0s[2][LH], c1s[2][LH];
    __shared__ float a0buf[2][G4], p1buf[2][G4], p2buf[2][G4];
    __shared__ float lasth[2][LH];
    __shared__ float r1s[2][32];
    __shared__ int lastidx[2];

    const int tid = threadIdx.x;
    const int m = tid >> 7;
    const int g = tid & 127;
    const int b0 = blockIdx.x * 2;

    const float* W = (m == 0) ? Whh0 : (m == 1) ? Wih1 : Whh1;
    ull wap[LH / 2], wbp[LH / 2];
#pragma unroll
    for (int k2 = 0; k2 < LH / 2; k2++)
        wap[k2] = pk2(W[g * LH + 2*k2], W[g * LH + 2*k2 + 1]);
#pragma unroll
    for (int k2 = 0; k2 < LH / 2; k2++)
        wbp[k2] = pk2(W[(g + 128) * LH + 2*k2], W[(g + 128) * LH + 2*k2 + 1]);
    float biasA = 0.f, biasB = 0.f;
    if (m == 2) { biasA = bih1[g] + bhh1[g]; biasB = bih1[g + 128] + bhh1[g + 128]; }

    if (tid < 2 * LH) {
        int bb = tid >> 6, j = tid & 63;
        h0s[bb][j] = 0.f; c0s[bb][j] = 0.f;
        h1s[bb][j] = 0.f; c1s[bb][j] = 0.f;
        lasth[bb][j] = 0.f;
    }
    if (tid < 2) {
        const int* mp = mask + (size_t)(b0 + tid) * Tt;
        int sum = 0;
        for (int tt = 0; tt < Tt; tt++) sum += mp[tt];
        lastidx[tid] = max(sum, 1) - 1;
    }
    __syncthreads();

    float xga[2], xgb[2];
    if (m == 0) {
#pragma unroll
        for (int bb = 0; bb < 2; bb++) {
            const float* xp = g_xg0 + (size_t)(b0 + bb) * Tt * G4;
            xga[bb] = xp[g]; xgb[bb] = xp[g + 128];
        }
    }

    for (int s = 0; s <= Tt; s++) {
        if (m == 0) {
            if (s < Tt) {
#pragma unroll
                for (int bb = 0; bb < 2; bb++) {
                    ull aA = pk2(xga[bb], 0.f), aB = pk2(xgb[bb], 0.f);
                    const ulonglong2* hp = (const ulonglong2*)h0s[bb];
#pragma unroll
                    for (int q = 0; q < 16; q++) {
                        ulonglong2 h = hp[q];
                        aA = fma2_(h.x, wap[2*q],     aA);
                        aA = fma2_(h.y, wap[2*q + 1], aA);
                        aB = fma2_(h.x, wbp[2*q],     aB);
                        aB = fma2_(h.y, wbp[2*q + 1], aB);
                    }
                    float lo, hi;
                    upk2(aA, lo, hi); a0buf[bb][g]       = lo + hi;
                    upk2(aB, lo, hi); a0buf[bb][g + 128] = lo + hi;
                }
                if (s + 1 < Tt) {
#pragma unroll
                    for (int bb = 0; bb < 2; bb++) {
                        const float* xp = g_xg0 + ((size_t)(b0 + bb) * Tt + (s + 1)) * G4;
                        xga[bb] = xp[g]; xgb[bb] = xp[g + 128];
                    }
                }
            }
        } else if (m == 1) {
            if (s >= 1) {
#pragma unroll
                for (int bb = 0; bb < 2; bb++) {
                    ull aA = 0ull, aB = 0ull;
                    const ulonglong2* hp = (const ulonglong2*)h0s[bb];
#pragma unroll
                    for (int q = 0; q < 16; q++) {
                        ulonglong2 h = hp[q];
                        aA = fma2_(h.x, wap[2*q],     aA);
                        aA = fma2_(h.y, wap[2*q + 1], aA);
                        aB = fma2_(h.x, wbp[2*q],     aB);
                        aB = fma2_(h.y, wbp[2*q + 1], aB);
                    }
                    float lo, hi;
                    upk2(aA, lo, hi); p1buf[bb][g]       = lo + hi;
                    upk2(aB, lo, hi); p1buf[bb][g + 128] = lo + hi;
                }
            }
        } else {
            if (s >= 1) {
#pragma unroll
                for (int bb = 0; bb < 2; bb++) {
                    ull aA = pk2(biasA, 0.f), aB = pk2(biasB, 0.f);
                    const ulonglong2* hp = (const ulonglong2*)h1s[bb];
#pragma unroll
                    for (int q = 0; q < 16; q++) {
                        ulonglong2 h = hp[q];
                        aA = fma2_(h.x, wap[2*q],     aA);
                        aA = fma2_(h.y, wap[2*q + 1], aA);
                        aB = fma2_(h.x, wbp[2*q],     aB);
                        aB = fma2_(h.y, wbp[2*q + 1], aB);
                    }
                    float lo, hi;
                    upk2(aA, lo, hi); p2buf[bb][g]       = lo + hi;
                    upk2(aB, lo, hi); p2buf[bb][g + 128] = lo + hi;
                }
            }
        }
        __syncthreads();

        if (m == 0 && s < Tt) {
            int bb = g >> 6, j = g & 63;
            float gi = a0buf[bb][j];
            float gf = a0buf[bb][j + 64];
            float gg = a0buf[bb][j + 128];
            float go = a0buf[bb][j + 192];
            float c = sigmoidf_(gf) * c0s[bb][j] + sigmoidf_(gi) * tanh_ap(gg);
            c0s[bb][j] = c;
            h0s[bb][j] = sigmoidf_(go) * tanh_ap(c);
        }
        if (m == 1 && s >= 1) {
            int bb = g >> 6, j = g & 63;
            float gi = p1buf[bb][j]       + p2buf[bb][j];
            float gf = p1buf[bb][j + 64]  + p2buf[bb][j + 64];
            float gg = p1buf[bb][j + 128] + p2buf[bb][j + 128];
            float go = p1buf[bb][j + 192] + p2buf[bb][j + 192];
            float c = sigmoidf_(gf) * c1s[bb][j] + sigmoidf_(gi) * tanh_ap(gg);
            c1s[bb][j] = c;
            float h = sigmoidf_(go) * tanh_ap(c);
            h1s[bb][j] = h;
            if (s - 1 == lastidx[bb]) lasth[bb][j] = h;
        }
        __syncthreads();
    }

    if (tid < 64) {
        int bb = tid >> 5, j = tid & 31;
        float acc = fc1_b[j];
#pragma unroll
        for (int k = 0; k < LH; k++) acc = fmaf(lasth[bb][k], fc1_w[j * LH + k], acc);
        r1s[bb][j] = fmaxf(acc, 0.f);
    }
    __syncthreads();
    if (tid < 4) {
        int bb = tid >> 1, o = tid & 1;
        float acc = fc2_b[o];
#pragma unroll
        for (int k = 0; k < 32; k++) acc = fmaf(r1s[bb][k], fc2_w[o * 32 + k], acc);
        out[(b0 + bb) * 2 + o] = acc;
    }
}

// ---------------------------------------------------------------------------
extern "C" void kernel_launch(void* const* d_in, const int* in_sizes, int n_in,
                              void* d_out, int out_size)
{
    const float* conn  = (const float*)d_in[0];
    const int*   mask  = (const int*)  d_in[1];
    const float* w1_w  = (const float*)d_in[2];
    const float* w1_b  = (const float*)d_in[3];
    const float* w2_w  = (const float*)d_in[4];
    const float* w2_b  = (const float*)d_in[5];
    const float* Wih0  = (const float*)d_in[6];
    const float* Whh0  = (const float*)d_in[7];
    const float* bih0  = (const float*)d_in[8];
    const float* bhh0  = (const float*)d_in[9];
    const float* Wih1  = (const float*)d_in[10];
    const float* Whh1  = (const float*)d_in[11];
    const float* bih1  = (const float*)d_in[12];
    const float* bhh1  = (const float*)d_in[13];
    const float* fc1_w = (const float*)d_in[14];
    const float* fc1_b = (const float*)d_in[15];
    const float* fc2_w = (const float*)d_in[16];
    const float* fc2_b = (const float*)d_in[17];
    float* out = (float*)d_out;

    (void)cudaFuncSetAttribute((const void*)encoder_kernel,
                               cudaFuncAttributePreferredSharedMemoryCarveout, 100);

    // 5 CTAs/SM x 148 SMs = 740 CTAs (persistent grid-stride)
    encoder_kernel<<<740, 64>>>(conn, mask, w1_w, w1_b, w2_w, w2_b);
    xg_kernel<<<BT / 64, 128>>>(Wih0, bih0, bhh0);
    lstm_kernel<<<Bb / 2, 384>>>(mask, Whh0, Wih1, Whh1, bih1, bhh1,
                                 fc1_w, fc1_b, fc2_w, fc2_b, out);
}

// round 16
// speedup vs baseline: 1.0810x; 1.0810x over previous
#include <cuda_runtime.h>
#include <cuda_bf16.h>
#include <cstdint>

#define Nn 19
#define GH 64
#define GE 64
#define Bb 256
#define Tt 256
#define BT (Bb*Tt)
#define LH 64
#define G4 256  // 4*LH

typedef unsigned long long ull;

// Scratch (device globals; no allocation allowed)
__device__ float g_emb[(size_t)BT * GE];     // (B*T, 64)
__device__ float g_xg0[(size_t)BT * G4];     // (B*T, 256)

// ---- packed f32x2 helpers -------------------------------------------------
__device__ __forceinline__ ull pk2(float lo, float hi) {
    ull r; asm("mov.b64 %0, {%1, %2};" : "=l"(r) : "f"(lo), "f"(hi)); return r;
}
__device__ __forceinline__ void upk2(ull v, float& lo, float& hi) {
    asm("mov.b64 {%0, %1}, %2;" : "=f"(lo), "=f"(hi) : "l"(v));
}
__device__ __forceinline__ ull fma2_(ull a, ull b, ull c) {
    ull d; asm("fma.rn.f32x2 %0, %1, %2, %3;" : "=l"(d) : "l"(a), "l"(b), "l"(c));
    return d;
}

// ---- fast transcendentals via MUFU tanh -----------------------------------
__device__ __forceinline__ float tanh_ap(float x) {
    float y; asm("tanh.approx.f32 %0, %1;" : "=f"(y) : "f"(x)); return y;
}
__device__ __forceinline__ float sigmoidf_(float x) {
    return fmaf(0.5f, tanh_ap(0.5f * x), 0.5f);
}

// ---------------------------------------------------------------------------
// Kernel 1: graph encoder — EXACT R11 proven version (414.6us, reproduced 4x):
// 2-warp CTA sharing one w1/w2 smem copy, in-place An, f32x2 node packing,
// ulonglong2 operand loads.
// ---------------------------------------------------------------------------
__global__ __launch_bounds__(64, 6)
void encoder_kernel(const float* __restrict__ conn, const int* __restrict__ mask,
                    const float* __restrict__ w1_w, const float* __restrict__ w1_b,
                    const float* __restrict__ w2_w, const float* __restrict__ w2_b)
{
    __shared__ __align__(16) float2 w2s2[GE][32];   // {w2[j][f], w2[j+32][f]}
    __shared__ __align__(16) float2 w1s2[Nn][32];   // {w1[j][k], w1[j+32][k]}
    __shared__ __align__(16) float AsT[2][Nn][20];  // [warp][k][i]; becomes An in place
    __shared__ __align__(16) float X1T[2][GE][20];
    __shared__ float dis[2][20];

    const int tid = threadIdx.x;
    const int w = tid >> 5;      // warp in CTA
    const int t = tid & 31;      // lane

    for (int idx = tid; idx < GE * 32; idx += 64) {
        int f = idx >> 5, j = idx & 31;
        w2s2[f][j] = make_float2(w2_w[j * GE + f], w2_w[(j + 32) * GE + f]);
    }
    for (int idx = tid; idx < Nn * 32; idx += 64) {
        int k = idx >> 5, j = idx & 31;
        w1s2[k][j] = make_float2(w1_w[j * Nn + k], w1_w[(j + 32) * Nn + k]);
    }
    if (t < Nn) AsT[w][t][19] = 0.f;   // pad lane (never rewritten)

    const float b1a_ = w1_b[t], b1b_ = w1_b[t + 32];
    const ull b1a = pk2(b1a_, b1a_), b1b = pk2(b1b_, b1b_);
    const float b2a_ = w2_b[t], b2b_ = w2_b[t + 32];
    const ull b2a = pk2(b2a_, b2a_), b2b = pk2(b2b_, b2b_);
    __syncthreads();

    for (int bt = blockIdx.x * 2 + w; bt < BT; bt += gridDim.x * 2) {
        // ---- load A transposed ----
        const float* A = conn + (size_t)bt * (Nn * Nn);
#pragma unroll
        for (int u = 0; u < 12; u++) {
            int idx = t + u * 32;
            if (idx < Nn * Nn) { int i = idx / Nn, k = idx - i * Nn; AsT[w][k][i] = A[idx]; }
        }
        __syncwarp();
        // ---- degree normalization factors ----
        if (t < Nn) {
            float d = 1.f;
#pragma unroll
            for (int k = 0; k < Nn; k++) d += AsT[w][k][t];
            dis[w][t] = rsqrtf(fmaxf(d, 1e-6f));
        }
        __syncwarp();

        // ---- H1 = A@W1^T + b1 (reads raw A; w1 from shared) ----
        ull aA[10], aB[10];
#pragma unroll
        for (int ip = 0; ip < 10; ip++) { aA[ip] = b1a; aB[ip] = b1b; }
#pragma unroll
        for (int k = 0; k < Nn; k++) {
            float2 wv = w1s2[k][t];
            const ull wA = pk2(wv.x, wv.x), wB = pk2(wv.y, wv.y);
            const ulonglong2* row = (const ulonglong2*)AsT[w][k];
#pragma unroll
            for (int q = 0; q < 5; q++) {
                ulonglong2 r = row[q];
                aA[2*q]   = fma2_(r.x, wA, aA[2*q]);
                aA[2*q+1] = fma2_(r.y, wA, aA[2*q+1]);
                aB[2*q]   = fma2_(r.x, wB, aB[2*q]);
                aB[2*q+1] = fma2_(r.y, wB, aB[2*q+1]);
            }
        }
        float HsA[20], HsB[20];
#pragma unroll
        for (int ip = 0; ip < 10; ip++) { upk2(aA[ip], HsA[2*ip], HsA[2*ip+1]); upk2(aB[ip], HsB[2*ip], HsB[2*ip+1]); }
        __syncwarp();   // all lanes finished reading raw A

        // ---- normalize A -> An IN PLACE ----
#pragma unroll
        for (int u = 0; u < 12; u++) {
            int idx = t + u * 32;
            if (idx < Nn * Nn) {
                int i = idx / Nn, k = idx - i * Nn;
                float a = AsT[w][k][i] + (i == k ? 1.f : 0.f);
                AsT[w][k][i] = a * dis[w][i] * dis[w][k];
            }
        }
        __syncwarp();

        // ---- X1 = relu(An @ H1) -> smem transposed ----
#pragma unroll
        for (int ip = 0; ip < 10; ip++) { aA[ip] = 0ull; aB[ip] = 0ull; }
#pragma unroll
        for (int k = 0; k < Nn; k++) {
            const ulonglong2* row = (const ulonglong2*)AsT[w][k];
            const ull hA = pk2(HsA[k], HsA[k]), hB = pk2(HsB[k], HsB[k]);
#pragma unroll
            for (int q = 0; q < 5; q++) {
                ulonglong2 r = row[q];
                aA[2*q]   = fma2_(r.x, hA, aA[2*q]);
                aA[2*q+1] = fma2_(r.y, hA, aA[2*q+1]);
                aB[2*q]   = fma2_(r.x, hB, aB[2*q]);
                aB[2*q+1] = fma2_(r.y, hB, aB[2*q+1]);
            }
        }
#pragma unroll
        for (int ip = 0; ip < 10; ip++) {
            float lo, hi;
            upk2(aA[ip], lo, hi);
            { float2 s; s.x = fmaxf(lo, 0.f); s.y = fmaxf(hi, 0.f); *(float2*)&X1T[w][t][2*ip] = s; }
            upk2(aB[ip], lo, hi);
            { float2 s; s.x = fmaxf(lo, 0.f); s.y = fmaxf(hi, 0.f); *(float2*)&X1T[w][t + 32][2*ip] = s; }
        }
        __syncwarp();

        // ---- H2 = X1@W2^T + b2 (w2 via one LDS.64 per f) ----
#pragma unroll
        for (int ip = 0; ip < 10; ip++) { aA[ip] = b2a; aB[ip] = b2b; }
#pragma unroll 8
        for (int f = 0; f < GE; f++) {
            float2 wv = w2s2[f][t];
            const ull wA = pk2(wv.x, wv.x), wB = pk2(wv.y, wv.y);
            const ulonglong2* row = (const ulonglong2*)X1T[w][f];
#pragma unroll
            for (int q = 0; q < 5; q++) {
                ulonglong2 r = row[q];
                aA[2*q]   = fma2_(r.x, wA, aA[2*q]);
                aA[2*q+1] = fma2_(r.y, wA, aA[2*q+1]);
                aB[2*q]   = fma2_(r.x, wB, aB[2*q]);
                aB[2*q+1] = fma2_(r.y, wB, aB[2*q+1]);
            }
        }
#pragma unroll
        for (int ip = 0; ip < 10; ip++) { upk2(aA[ip], HsA[2*ip], HsA[2*ip+1]); upk2(aB[ip], HsB[2*ip], HsB[2*ip+1]); }

        // ---- X2 = relu(An @ H2); mean over nodes; mask ----
#pragma unroll
        for (int ip = 0; ip < 10; ip++) { aA[ip] = 0ull; aB[ip] = 0ull; }
#pragma unroll
        for (int k = 0; k < Nn; k++) {
            const ulonglong2* row = (const ulonglong2*)AsT[w][k];
            const ull hA = pk2(HsA[k], HsA[k]), hB = pk2(HsB[k], HsB[k]);
#pragma unroll
            for (int q = 0; q < 5; q++) {
                ulonglong2 r = row[q];
                aA[2*q]   = fma2_(r.x, hA, aA[2*q]);
                aA[2*q+1] = fma2_(r.y, hA, aA[2*q+1]);
                aB[2*q]   = fma2_(r.x, hB, aB[2*q]);
                aB[2*q+1] = fma2_(r.y, hB, aB[2*q+1]);
            }
        }
        float sA = 0.f, sB = 0.f;
#pragma unroll
        for (int ip = 0; ip < 10; ip++) {
            float lo, hi;
            upk2(aA[ip], lo, hi); sA += fmaxf(lo, 0.f) + fmaxf(hi, 0.f);
            upk2(aB[ip], lo, hi); sB += fmaxf(lo, 0.f) + fmaxf(hi, 0.f);
        }
        const float mf = (float)mask[bt] * (1.f / 19.f);
        g_emb[(size_t)bt * GE + t]      = sA * mf;
        g_emb[(size_t)bt * GE + t + 32] = sB * mf;
        __syncwarp();
    }
}

// ---------------------------------------------------------------------------
// Kernel 2: xg0 = emb @ Wih0^T + (bih0+bhh0) — exact R11 version.
// ---------------------------------------------------------------------------
__global__ __launch_bounds__(128, 2)
void xg_kernel(const float* __restrict__ Wih0, const float* __restrict__ bih0,
               const float* __restrict__ bhh0)
{
    __shared__ __align__(16) float es[64 * GE];
    const int t = threadIdx.x;
    ull wp1[GE / 2], wp2[GE / 2];
#pragma unroll
    for (int k2 = 0; k2 < GE / 2; k2++)
        wp1[k2] = pk2(Wih0[t * GE + 2*k2], Wih0[t * GE + 2*k2 + 1]);
#pragma unroll
    for (int k2 = 0; k2 < GE / 2; k2++)
        wp2[k2] = pk2(Wih0[(t + 128) * GE + 2*k2], Wih0[(t + 128) * GE + 2*k2 + 1]);
    const float bias1 = bih0[t] + bhh0[t];
    const float bias2 = bih0[t + 128] + bhh0[t + 128];

    const float* ep = g_emb + (size_t)blockIdx.x * 64 * GE;
    for (int idx = t; idx < 64 * GE; idx += 128) es[idx] = ep[idx];
    __syncthreads();

    float* op = g_xg0 + (size_t)blockIdx.x * 64 * G4;
    for (int r = 0; r < 64; r++) {
        ull a1 = pk2(bias1, 0.f), a2 = pk2(bias2, 0.f);
        const ulonglong2* row = (const ulonglong2*)&es[r * GE];
#pragma unroll
        for (int q = 0; q < 16; q++) {
            ulonglong2 e = row[q];
            a1 = fma2_(e.x, wp1[2*q],     a1);
            a1 = fma2_(e.y, wp1[2*q + 1], a1);
            a2 = fma2_(e.x, wp2[2*q],     a2);
            a2 = fma2_(e.y, wp2[2*q + 1], a2);
        }
        float lo, hi;
        upk2(a1, lo, hi); op[r * G4 + t]       = lo + hi;
        upk2(a2, lo, hi); op[r * G4 + t + 128] = lo + hi;
    }
}

// ---------------------------------------------------------------------------
// Kernel 3: fused 2-layer LSTM + FC head, restructured synchronization:
//  - h0/h1 state DOUBLE-BUFFERED -> g0's update no longer anti-depends on
//    g1/g2's reads; groups sync privately via NAMED barriers
//    (bar.sync 1,128 for g0; bar.sync 2,256 for g1+g2), then ONE CTA-wide
//    __syncthreads per step (was two).
//  - cell states c0/c1 live in REGISTERS (single owner thread each).
// Weight layout / compute bodies identical to the proven R11 version.
// ---------------------------------------------------------------------------
__global__ __launch_bounds__(384, 1)
void lstm_kernel(const int* __restrict__ mask,
                 const float* __restrict__ Whh0,
                 const float* __restrict__ Wih1, const float* __restrict__ Whh1,
                 const float* __restrict__ bih1, const float* __restrict__ bhh1,
                 const float* __restrict__ fc1_w, const float* __restrict__ fc1_b,
                 const float* __restrict__ fc2_w, const float* __restrict__ fc2_b,
                 float* __restrict__ out)
{
    __shared__ __align__(16) float h0s[2][2][LH];   // [buf][bb][j]
    __shared__ __align__(16) float h1s[2][2][LH];
    __shared__ float a0buf[2][G4], p1buf[2][G4], p2buf[2][G4];
    __shared__ float lasth[2][LH];
    __shared__ float r1s[2][32];
    __shared__ int lastidx[2];

    const int tid = threadIdx.x;
    const int m = tid >> 7;
    const int g = tid & 127;
    const int b0 = blockIdx.x * 2;

    const float* W = (m == 0) ? Whh0 : (m == 1) ? Wih1 : Whh1;
    ull wap[LH / 2], wbp[LH / 2];
#pragma unroll
    for (int k2 = 0; k2 < LH / 2; k2++)
        wap[k2] = pk2(W[g * LH + 2*k2], W[g * LH + 2*k2 + 1]);
#pragma unroll
    for (int k2 = 0; k2 < LH / 2; k2++)
        wbp[k2] = pk2(W[(g + 128) * LH + 2*k2], W[(g + 128) * LH + 2*k2 + 1]);
    float biasA = 0.f, biasB = 0.f;
    if (m == 2) { biasA = bih1[g] + bhh1[g]; biasB = bih1[g + 128] + bhh1[g + 128]; }

    // zero both buffers of h0/h1, and lasth
    for (int idx = tid; idx < 2 * 2 * LH; idx += 384) {
        ((float*)h0s)[idx] = 0.f;
        ((float*)h1s)[idx] = 0.f;
    }
    if (tid < 2 * LH) ((float*)lasth)[tid] = 0.f;
    if (tid < 2) {
        const int* mp = mask + (size_t)(b0 + tid) * Tt;
        int sum = 0;
        for (int tt = 0; tt < Tt; tt++) sum += mp[tt];
        lastidx[tid] = max(sum, 1) - 1;
    }
    __syncthreads();

    // register-resident cell state (owner: thread g of its group)
    float creg = 0.f;

    float xga[2], xgb[2];
    if (m == 0) {
#pragma unroll
        for (int bb = 0; bb < 2; bb++) {
            const float* xp = g_xg0 + (size_t)(b0 + bb) * Tt * G4;
            xga[bb] = xp[g]; xgb[bb] = xp[g + 128];
        }
    }

    for (int s = 0; s <= Tt; s++) {
        const int cur = s & 1, nxt = cur ^ 1;
        if (m == 0) {
            if (s < Tt) {
#pragma unroll
                for (int bb = 0; bb < 2; bb++) {
                    ull aA = pk2(xga[bb], 0.f), aB = pk2(xgb[bb], 0.f);
                    const ulonglong2* hp = (const ulonglong2*)h0s[cur][bb];
#pragma unroll
                    for (int q = 0; q < 16; q++) {
                        ulonglong2 h = hp[q];
                        aA = fma2_(h.x, wap[2*q],     aA);
                        aA = fma2_(h.y, wap[2*q + 1], aA);
                        aB = fma2_(h.x, wbp[2*q],     aB);
                        aB = fma2_(h.y, wbp[2*q + 1], aB);
                    }
                    float lo, hi;
                    upk2(aA, lo, hi); a0buf[bb][g]       = lo + hi;
                    upk2(aB, lo, hi); a0buf[bb][g + 128] = lo + hi;
                }
                if (s + 1 < Tt) {
#pragma unroll
                    for (int bb = 0; bb < 2; bb++) {
                        const float* xp = g_xg0 + ((size_t)(b0 + bb) * Tt + (s + 1)) * G4;
                        xga[bb] = xp[g]; xgb[bb] = xp[g + 128];
                    }
                }
            }
            asm volatile("bar.sync 1, 128;" ::: "memory");   // g0 internal
            if (s < Tt) {
                int bb = g >> 6, j = g & 63;
                float gi = a0buf[bb][j];
                float gf = a0buf[bb][j + 64];
                float gg = a0buf[bb][j + 128];
                float go = a0buf[bb][j + 192];
                creg = sigmoidf_(gf) * creg + sigmoidf_(gi) * tanh_ap(gg);
                h0s[nxt][bb][j] = sigmoidf_(go) * tanh_ap(creg);
            }
        } else if (m == 1) {
            if (s >= 1) {
#pragma unroll
                for (int bb = 0; bb < 2; bb++) {
                    ull aA = 0ull, aB = 0ull;
                    const ulonglong2* hp = (const ulonglong2*)h0s[cur][bb];
#pragma unroll
                    for (int q = 0; q < 16; q++) {
                        ulonglong2 h = hp[q];
                        aA = fma2_(h.x, wap[2*q],     aA);
                        aA = fma2_(h.y, wap[2*q + 1], aA);
                        aB = fma2_(h.x, wbp[2*q],     aB);
                        aB = fma2_(h.y, wbp[2*q + 1], aB);
                    }
                    float lo, hi;
                    upk2(aA, lo, hi); p1buf[bb][g]       = lo + hi;
                    upk2(aB, lo, hi); p1buf[bb][g + 128] = lo + hi;
                }
            }
            asm volatile("bar.sync 2, 256;" ::: "memory");   // g1+g2
            if (s >= 1) {
                int bb = g >> 6, j = g & 63;
                float gi = p1buf[bb][j]       + p2buf[bb][j];
                float gf = p1buf[bb][j + 64]  + p2buf[bb][j + 64];
                float gg = p1buf[bb][j + 128] + p2buf[bb][j + 128];
                float go = p1buf[bb][j + 192] + p2buf[bb][j + 192];
                creg = sigmoidf_(gf) * creg + sigmoidf_(gi) * tanh_ap(gg);
                float h = sigmoidf_(go) * tanh_ap(creg);
                h1s[nxt][bb][j] = h;
                if (s - 1 == lastidx[bb]) lasth[bb][j] = h;
            }
        } else {
            if (s >= 1) {
#pragma unroll
                for (int bb = 0; bb < 2; bb++) {
                    ull aA = pk2(biasA, 0.f), aB = pk2(biasB, 0.f);
                    const ulonglong2* hp = (const ulonglong2*)h1s[cur][bb];
#pragma unroll
                    for (int q = 0; q < 16; q++) {
                        ulonglong2 h = hp[q];
                        aA = fma2_(h.x, wap[2*q],     aA);
                        aA = fma2_(h.y, wap[2*q + 1], aA);
                        aB = fma2_(h.x, wbp[2*q],     aB);
                        aB = fma2_(h.y, wbp[2*q + 1], aB);
                    }
                    float lo, hi;
                    upk2(aA, lo, hi); p2buf[bb][g]       = lo + hi;
                    upk2(aB, lo, hi); p2buf[bb][g + 128] = lo + hi;
                }
            }
            asm volatile("bar.sync 2, 256;" ::: "memory");   // g1+g2
        }
        __syncthreads();   // publish h0s[nxt], h1s[nxt] to all groups
    }

    if (tid < 64) {
        int bb = tid >> 5, j = tid & 31;
        float acc = fc1_b[j];
#pragma unroll
        for (int k = 0; k < LH; k++) acc = fmaf(lasth[bb][k], fc1_w[j * LH + k], acc);
        r1s[bb][j] = fmaxf(acc, 0.f);
    }
    __syncthreads();
    if (tid < 4) {
        int bb = tid >> 1, o = tid & 1;
        float acc = fc2_b[o];
#pragma unroll
        for (int k = 0; k < 32; k++) acc = fmaf(r1s[bb][k], fc2_w[o * 32 + k], acc);
        out[(b0 + bb) * 2 + o] = acc;
    }
}

// ---------------------------------------------------------------------------
extern "C" void kernel_launch(void* const* d_in, const int* in_sizes, int n_in,
                              void* d_out, int out_size)
{
    const float* conn  = (const float*)d_in[0];
    const int*   mask  = (const int*)  d_in[1];
    const float* w1_w  = (const float*)d_in[2];
    const float* w1_b  = (const float*)d_in[3];
    const float* w2_w  = (const float*)d_in[4];
    const float* w2_b  = (const float*)d_in[5];
    const float* Wih0  = (const float*)d_in[6];
    const float* Whh0  = (const float*)d_in[7];
    const float* bih0  = (const float*)d_in[8];
    const float* bhh0  = (const float*)d_in[9];
    const float* Wih1  = (const float*)d_in[10];
    const float* Whh1  = (const float*)d_in[11];
    const float* bih1  = (const float*)d_in[12];
    const float* bhh1  = (const float*)d_in[13];
    const float* fc1_w = (const float*)d_in[14];
    const float* fc1_b = (const float*)d_in[15];
    const float* fc2_w = (const float*)d_in[16];
    const float* fc2_b = (const float*)d_in[17];
    float* out = (float*)d_out;

    (void)cudaFuncSetAttribute((const void*)encoder_kernel,
                               cudaFuncAttributePreferredSharedMemoryCarveout, 100);

    encoder_kernel<<<888, 64>>>(conn, mask, w1_w, w1_b, w2_w, w2_b);
    xg_kernel<<<BT / 64, 128>>>(Wih0, bih0, bhh0);
    lstm_kernel<<<Bb / 2, 384>>>(mask, Whh0, Wih1, Whh1, bih1, bhh1,
                                 fc1_w, fc1_b, fc2_w, fc2_b, out);
}

// round 17
// speedup vs baseline: 1.0817x; 1.0006x over previous
#include <cuda_runtime.h>
#include <cuda_bf16.h>
#include <cstdint>

#define Nn 19
#define GH 64
#define GE 64
#define Bb 256
#define Tt 256
#define BT (Bb*Tt)
#define LH 64
#define G4 256  // 4*LH

typedef unsigned long long ull;

// Scratch (device globals; no allocation allowed)
__device__ float g_emb[(size_t)BT * GE];     // (B*T, 64)
__device__ float g_xg0[(size_t)BT * G4];     // (B*T, 256)

// ---- packed f32x2 helpers -------------------------------------------------
__device__ __forceinline__ ull pk2(float lo, float hi) {
    ull r; asm("mov.b64 %0, {%1, %2};" : "=l"(r) : "f"(lo), "f"(hi)); return r;
}
__device__ __forceinline__ void upk2(ull v, float& lo, float& hi) {
    asm("mov.b64 {%0, %1}, %2;" : "=f"(lo), "=f"(hi) : "l"(v));
}
__device__ __forceinline__ ull fma2_(ull a, ull b, ull c) {
    ull d; asm("fma.rn.f32x2 %0, %1, %2, %3;" : "=l"(d) : "l"(a), "l"(b), "l"(c));
    return d;
}

// ---- fast transcendentals via MUFU tanh -----------------------------------
__device__ __forceinline__ float tanh_ap(float x) {
    float y; asm("tanh.approx.f32 %0, %1;" : "=f"(y) : "f"(x)); return y;
}
__device__ __forceinline__ float sigmoidf_(float x) {
    return fmaf(0.5f, tanh_ap(0.5f * x), 0.5f);
}

// ---------------------------------------------------------------------------
// Kernel 1: graph encoder — EXACT R11/R16 proven version (415us, 5x):
// 2-warp CTA sharing one w1/w2 smem copy, in-place An, f32x2 node packing,
// ulonglong2 operand loads.
// ---------------------------------------------------------------------------
__global__ __launch_bounds__(64, 6)
void encoder_kernel(const float* __restrict__ conn, const int* __restrict__ mask,
                    const float* __restrict__ w1_w, const float* __restrict__ w1_b,
                    const float* __restrict__ w2_w, const float* __restrict__ w2_b)
{
    __shared__ __align__(16) float2 w2s2[GE][32];   // {w2[j][f], w2[j+32][f]}
    __shared__ __align__(16) float2 w1s2[Nn][32];   // {w1[j][k], w1[j+32][k]}
    __shared__ __align__(16) float AsT[2][Nn][20];  // [warp][k][i]; becomes An in place
    __shared__ __align__(16) float X1T[2][GE][20];
    __shared__ float dis[2][20];

    const int tid = threadIdx.x;
    const int w = tid >> 5;      // warp in CTA
    const int t = tid & 31;      // lane

    for (int idx = tid; idx < GE * 32; idx += 64) {
        int f = idx >> 5, j = idx & 31;
        w2s2[f][j] = make_float2(w2_w[j * GE + f], w2_w[(j + 32) * GE + f]);
    }
    for (int idx = tid; idx < Nn * 32; idx += 64) {
        int k = idx >> 5, j = idx & 31;
        w1s2[k][j] = make_float2(w1_w[j * Nn + k], w1_w[(j + 32) * Nn + k]);
    }
    if (t < Nn) AsT[w][t][19] = 0.f;   // pad lane (never rewritten)

    const float b1a_ = w1_b[t], b1b_ = w1_b[t + 32];
    const ull b1a = pk2(b1a_, b1a_), b1b = pk2(b1b_, b1b_);
    const float b2a_ = w2_b[t], b2b_ = w2_b[t + 32];
    const ull b2a = pk2(b2a_, b2a_), b2b = pk2(b2b_, b2b_);
    __syncthreads();

    for (int bt = blockIdx.x * 2 + w; bt < BT; bt += gridDim.x * 2) {
        // ---- load A transposed ----
        const float* A = conn + (size_t)bt * (Nn * Nn);
#pragma unroll
        for (int u = 0; u < 12; u++) {
            int idx = t + u * 32;
            if (idx < Nn * Nn) { int i = idx / Nn, k = idx - i * Nn; AsT[w][k][i] = A[idx]; }
        }
        __syncwarp();
        // ---- degree normalization factors ----
        if (t < Nn) {
            float d = 1.f;
#pragma unroll
            for (int k = 0; k < Nn; k++) d += AsT[w][k][t];
            dis[w][t] = rsqrtf(fmaxf(d, 1e-6f));
        }
        __syncwarp();

        // ---- H1 = A@W1^T + b1 (reads raw A; w1 from shared) ----
        ull aA[10], aB[10];
#pragma unroll
        for (int ip = 0; ip < 10; ip++) { aA[ip] = b1a; aB[ip] = b1b; }
#pragma unroll
        for (int k = 0; k < Nn; k++) {
            float2 wv = w1s2[k][t];
            const ull wA = pk2(wv.x, wv.x), wB = pk2(wv.y, wv.y);
            const ulonglong2* row = (const ulonglong2*)AsT[w][k];
#pragma unroll
            for (int q = 0; q < 5; q++) {
                ulonglong2 r = row[q];
                aA[2*q]   = fma2_(r.x, wA, aA[2*q]);
                aA[2*q+1] = fma2_(r.y, wA, aA[2*q+1]);
                aB[2*q]   = fma2_(r.x, wB, aB[2*q]);
                aB[2*q+1] = fma2_(r.y, wB, aB[2*q+1]);
            }
        }
        float HsA[20], HsB[20];
#pragma unroll
        for (int ip = 0; ip < 10; ip++) { upk2(aA[ip], HsA[2*ip], HsA[2*ip+1]); upk2(aB[ip], HsB[2*ip], HsB[2*ip+1]); }
        __syncwarp();   // all lanes finished reading raw A

        // ---- normalize A -> An IN PLACE ----
#pragma unroll
        for (int u = 0; u < 12; u++) {
            int idx = t + u * 32;
            if (idx < Nn * Nn) {
                int i = idx / Nn, k = idx - i * Nn;
                float a = AsT[w][k][i] + (i == k ? 1.f : 0.f);
                AsT[w][k][i] = a * dis[w][i] * dis[w][k];
            }
        }
        __syncwarp();

        // ---- X1 = relu(An @ H1) -> smem transposed ----
#pragma unroll
        for (int ip = 0; ip < 10; ip++) { aA[ip] = 0ull; aB[ip] = 0ull; }
#pragma unroll
        for (int k = 0; k < Nn; k++) {
            const ulonglong2* row = (const ulonglong2*)AsT[w][k];
            const ull hA = pk2(HsA[k], HsA[k]), hB = pk2(HsB[k], HsB[k]);
#pragma unroll
            for (int q = 0; q < 5; q++) {
                ulonglong2 r = row[q];
                aA[2*q]   = fma2_(r.x, hA, aA[2*q]);
                aA[2*q+1] = fma2_(r.y, hA, aA[2*q+1]);
                aB[2*q]   = fma2_(r.x, hB, aB[2*q]);
                aB[2*q+1] = fma2_(r.y, hB, aB[2*q+1]);
            }
        }
#pragma unroll
        for (int ip = 0; ip < 10; ip++) {
            float lo, hi;
            upk2(aA[ip], lo, hi);
            { float2 s; s.x = fmaxf(lo, 0.f); s.y = fmaxf(hi, 0.f); *(float2*)&X1T[w][t][2*ip] = s; }
            upk2(aB[ip], lo, hi);
            { float2 s; s.x = fmaxf(lo, 0.f); s.y = fmaxf(hi, 0.f); *(float2*)&X1T[w][t + 32][2*ip] = s; }
        }
        __syncwarp();

        // ---- H2 = X1@W2^T + b2 (w2 via one LDS.64 per f) ----
#pragma unroll
        for (int ip = 0; ip < 10; ip++) { aA[ip] = b2a; aB[ip] = b2b; }
#pragma unroll 8
        for (int f = 0; f < GE; f++) {
            float2 wv = w2s2[f][t];
            const ull wA = pk2(wv.x, wv.x), wB = pk2(wv.y, wv.y);
            const ulonglong2* row = (const ulonglong2*)X1T[w][f];
#pragma unroll
            for (int q = 0; q < 5; q++) {
                ulonglong2 r = row[q];
                aA[2*q]   = fma2_(r.x, wA, aA[2*q]);
                aA[2*q+1] = fma2_(r.y, wA, aA[2*q+1]);
                aB[2*q]   = fma2_(r.x, wB, aB[2*q]);
                aB[2*q+1] = fma2_(r.y, wB, aB[2*q+1]);
            }
        }
#pragma unroll
        for (int ip = 0; ip < 10; ip++) { upk2(aA[ip], HsA[2*ip], HsA[2*ip+1]); upk2(aB[ip], HsB[2*ip], HsB[2*ip+1]); }

        // ---- X2 = relu(An @ H2); mean over nodes; mask ----
#pragma unroll
        for (int ip = 0; ip < 10; ip++) { aA[ip] = 0ull; aB[ip] = 0ull; }
#pragma unroll
        for (int k = 0; k < Nn; k++) {
            const ulonglong2* row = (const ulonglong2*)AsT[w][k];
            const ull hA = pk2(HsA[k], HsA[k]), hB = pk2(HsB[k], HsB[k]);
#pragma unroll
            for (int q = 0; q < 5; q++) {
                ulonglong2 r = row[q];
                aA[2*q]   = fma2_(r.x, hA, aA[2*q]);
                aA[2*q+1] = fma2_(r.y, hA, aA[2*q+1]);
                aB[2*q]   = fma2_(r.x, hB, aB[2*q]);
                aB[2*q+1] = fma2_(r.y, hB, aB[2*q+1]);
            }
        }
        float sA = 0.f, sB = 0.f;
#pragma unroll
        for (int ip = 0; ip < 10; ip++) {
            float lo, hi;
            upk2(aA[ip], lo, hi); sA += fmaxf(lo, 0.f) + fmaxf(hi, 0.f);
            upk2(aB[ip], lo, hi); sB += fmaxf(lo, 0.f) + fmaxf(hi, 0.f);
        }
        const float mf = (float)mask[bt] * (1.f / 19.f);
        g_emb[(size_t)bt * GE + t]      = sA * mf;
        g_emb[(size_t)bt * GE + t + 32] = sB * mf;
        __syncwarp();
    }
}

// ---------------------------------------------------------------------------
// Kernel 2: xg0 = emb @ Wih0^T + (bih0+bhh0).
// NEW: 2-row ILP (two independent accumulator sets sharing register weights)
// + 3 CTAs/SM (launch_bounds(128,3)) to cover LDS latency.
// ---------------------------------------------------------------------------
__global__ __launch_bounds__(128, 3)
void xg_kernel(const float* __restrict__ Wih0, const float* __restrict__ bih0,
               const float* __restrict__ bhh0)
{
    __shared__ __align__(16) float es[64 * GE];
    const int t = threadIdx.x;
    ull wp1[GE / 2], wp2[GE / 2];
#pragma unroll
    for (int k2 = 0; k2 < GE / 2; k2++)
        wp1[k2] = pk2(Wih0[t * GE + 2*k2], Wih0[t * GE + 2*k2 + 1]);
#pragma unroll
    for (int k2 = 0; k2 < GE / 2; k2++)
        wp2[k2] = pk2(Wih0[(t + 128) * GE + 2*k2], Wih0[(t + 128) * GE + 2*k2 + 1]);
    const float bias1 = bih0[t] + bhh0[t];
    const float bias2 = bih0[t + 128] + bhh0[t + 128];

    const float* ep = g_emb + (size_t)blockIdx.x * 64 * GE;
    for (int idx = t; idx < 64 * GE; idx += 128) es[idx] = ep[idx];
    __syncthreads();

    float* op = g_xg0 + (size_t)blockIdx.x * 64 * G4;
    for (int r = 0; r < 64; r += 2) {
        ull a1 = pk2(bias1, 0.f), a2 = pk2(bias2, 0.f);   // row r
        ull a3 = pk2(bias1, 0.f), a4 = pk2(bias2, 0.f);   // row r+1
        const ulonglong2* row0 = (const ulonglong2*)&es[r * GE];
        const ulonglong2* row1 = (const ulonglong2*)&es[(r + 1) * GE];
#pragma unroll
        for (int q = 0; q < 16; q++) {
            ulonglong2 e0 = row0[q];
            ulonglong2 e1 = row1[q];
            a1 = fma2_(e0.x, wp1[2*q],     a1);
            a1 = fma2_(e0.y, wp1[2*q + 1], a1);
            a2 = fma2_(e0.x, wp2[2*q],     a2);
            a2 = fma2_(e0.y, wp2[2*q + 1], a2);
            a3 = fma2_(e1.x, wp1[2*q],     a3);
            a3 = fma2_(e1.y, wp1[2*q + 1], a3);
            a4 = fma2_(e1.x, wp2[2*q],     a4);
            a4 = fma2_(e1.y, wp2[2*q + 1], a4);
        }
        float lo, hi;
        upk2(a1, lo, hi); op[r * G4 + t]             = lo + hi;
        upk2(a2, lo, hi); op[r * G4 + t + 128]       = lo + hi;
        upk2(a3, lo, hi); op[(r + 1) * G4 + t]       = lo + hi;
        upk2(a4, lo, hi); op[(r + 1) * G4 + t + 128] = lo + hi;
    }
}

// ---------------------------------------------------------------------------
// Kernel 3: fused 2-layer LSTM + FC head — EXACT R16 winning version:
// double-buffered h state, named per-group barriers + one CTA-wide barrier
// per step, register-resident cell state, MUFU tanh.approx.
// ---------------------------------------------------------------------------
__global__ __launch_bounds__(384, 1)
void lstm_kernel(const int* __restrict__ mask,
                 const float* __restrict__ Whh0,
                 const float* __restrict__ Wih1, const float* __restrict__ Whh1,
                 const float* __restrict__ bih1, const float* __restrict__ bhh1,
                 const float* __restrict__ fc1_w, const float* __restrict__ fc1_b,
                 const float* __restrict__ fc2_w, const float* __restrict__ fc2_b,
                 float* __restrict__ out)
{
    __shared__ __align__(16) float h0s[2][2][LH];   // [buf][bb][j]
    __shared__ __align__(16) float h1s[2][2][LH];
    __shared__ float a0buf[2][G4], p1buf[2][G4], p2buf[2][G4];
    __shared__ float lasth[2][LH];
    __shared__ float r1s[2][32];
    __shared__ int lastidx[2];

    const int tid = threadIdx.x;
    const int m = tid >> 7;
    const int g = tid & 127;
    const int b0 = blockIdx.x * 2;

    const float* W = (m == 0) ? Whh0 : (m == 1) ? Wih1 : Whh1;
    ull wap[LH / 2], wbp[LH / 2];
#pragma unroll
    for (int k2 = 0; k2 < LH / 2; k2++)
        wap[k2] = pk2(W[g * LH + 2*k2], W[g * LH + 2*k2 + 1]);
#pragma unroll
    for (int k2 = 0; k2 < LH / 2; k2++)
        wbp[k2] = pk2(W[(g + 128) * LH + 2*k2], W[(g + 128) * LH + 2*k2 + 1]);
    float biasA = 0.f, biasB = 0.f;
    if (m == 2) { biasA = bih1[g] + bhh1[g]; biasB = bih1[g + 128] + bhh1[g + 128]; }

    // zero both buffers of h0/h1, and lasth
    for (int idx = tid; idx < 2 * 2 * LH; idx += 384) {
        ((float*)h0s)[idx] = 0.f;
        ((float*)h1s)[idx] = 0.f;
    }
    if (tid < 2 * LH) ((float*)lasth)[tid] = 0.f;
    if (tid < 2) {
        const int* mp = mask + (size_t)(b0 + tid) * Tt;
        int sum = 0;
        for (int tt = 0; tt < Tt; tt++) sum += mp[tt];
        lastidx[tid] = max(sum, 1) - 1;
    }
    __syncthreads();

    // register-resident cell state (owner: thread g of its group)
    float creg = 0.f;

    float xga[2], xgb[2];
    if (m == 0) {
#pragma unroll
        for (int bb = 0; bb < 2; bb++) {
            const float* xp = g_xg0 + (size_t)(b0 + bb) * Tt * G4;
            xga[bb] = xp[g]; xgb[bb] = xp[g + 128];
        }
    }

    for (int s = 0; s <= Tt; s++) {
        const int cur = s & 1, nxt = cur ^ 1;
        if (m == 0) {
            if (s < Tt) {
#pragma unroll
                for (int bb = 0; bb < 2; bb++) {
                    ull aA = pk2(xga[bb], 0.f), aB = pk2(xgb[bb], 0.f);
                    const ulonglong2* hp = (const ulonglong2*)h0s[cur][bb];
#pragma unroll
                    for (int q = 0; q < 16; q++) {
                        ulonglong2 h = hp[q];
                        aA = fma2_(h.x, wap[2*q],     aA);
                        aA = fma2_(h.y, wap[2*q + 1], aA);
                        aB = fma2_(h.x, wbp[2*q],     aB);
                        aB = fma2_(h.y, wbp[2*q + 1], aB);
                    }
                    float lo, hi;
                    upk2(aA, lo, hi); a0buf[bb][g]       = lo + hi;
                    upk2(aB, lo, hi); a0buf[bb][g + 128] = lo + hi;
                }
                if (s + 1 < Tt) {
#pragma unroll
                    for (int bb = 0; bb < 2; bb++) {
                        const float* xp = g_xg0 + ((size_t)(b0 + bb) * Tt + (s + 1)) * G4;
                        xga[bb] = xp[g]; xgb[bb] = xp[g + 128];
                    }
                }
            }
            asm volatile("bar.sync 1, 128;" ::: "memory");   // g0 internal
            if (s < Tt) {
                int bb = g >> 6, j = g & 63;
                float gi = a0buf[bb][j];
                float gf = a0buf[bb][j + 64];
                float gg = a0buf[bb][j + 128];
                float go = a0buf[bb][j + 192];
                creg = sigmoidf_(gf) * creg + sigmoidf_(gi) * tanh_ap(gg);
                h0s[nxt][bb][j] = sigmoidf_(go) * tanh_ap(creg);
            }
        } else if (m == 1) {
            if (s >= 1) {
#pragma unroll
                for (int bb = 0; bb < 2; bb++) {
                    ull aA = 0ull, aB = 0ull;
                    const ulonglong2* hp = (const ulonglong2*)h0s[cur][bb];
#pragma unroll
                    for (int q = 0; q < 16; q++) {
                        ulonglong2 h = hp[q];
                        aA = fma2_(h.x, wap[2*q],     aA);
                        aA = fma2_(h.y, wap[2*q + 1], aA);
                        aB = fma2_(h.x, wbp[2*q],     aB);
                        aB = fma2_(h.y, wbp[2*q + 1], aB);
                    }
                    float lo, hi;
                    upk2(aA, lo, hi); p1buf[bb][g]       = lo + hi;
                    upk2(aB, lo, hi); p1buf[bb][g + 128] = lo + hi;
                }
            }
            asm volatile("bar.sync 2, 256;" ::: "memory");   // g1+g2
            if (s >= 1) {
                int bb = g >> 6, j = g & 63;
                float gi = p1buf[bb][j]       + p2buf[bb][j];
                float gf = p1buf[bb][j + 64]  + p2buf[bb][j + 64];
                float gg = p1buf[bb][j + 128] + p2buf[bb][j + 128];
                float go = p1buf[bb][j + 192] + p2buf[bb][j + 192];
                creg = sigmoidf_(gf) * creg + sigmoidf_(gi) * tanh_ap(gg);
                float h = sigmoidf_(go) * tanh_ap(creg);
                h1s[nxt][bb][j] = h;
                if (s - 1 == lastidx[bb]) lasth[bb][j] = h;
            }
        } else {
            if (s >= 1) {
#pragma unroll
                for (int bb = 0; bb < 2; bb++) {
                    ull aA = pk2(biasA, 0.f), aB = pk2(biasB, 0.f);
                    const ulonglong2* hp = (const ulonglong2*)h1s[cur][bb];
#pragma unroll
                    for (int q = 0; q < 16; q++) {
                        ulonglong2 h = hp[q];
                        aA = fma2_(h.x, wap[2*q],     aA);
                        aA = fma2_(h.y, wap[2*q + 1], aA);
                        aB = fma2_(h.x, wbp[2*q],     aB);
                        aB = fma2_(h.y, wbp[2*q + 1], aB);
                    }
                    float lo, hi;
                    upk2(aA, lo, hi); p2buf[bb][g]       = lo + hi;
                    upk2(aB, lo, hi); p2buf[bb][g + 128] = lo + hi;
                }
            }
            asm volatile("bar.sync 2, 256;" ::: "memory");   // g1+g2
        }
        __syncthreads();   // publish h0s[nxt], h1s[nxt] to all groups
    }

    if (tid < 64) {
        int bb = tid >> 5, j = tid & 31;
        float acc = fc1_b[j];
#pragma unroll
        for (int k = 0; k < LH; k++) acc = fmaf(lasth[bb][k], fc1_w[j * LH + k], acc);
        r1s[bb][j] = fmaxf(acc, 0.f);
    }
    __syncthreads();
    if (tid < 4) {
        int bb = tid >> 1, o = tid & 1;
        float acc = fc2_b[o];
#pragma unroll
        for (int k = 0; k < 32; k++) acc = fmaf(r1s[bb][k], fc2_w[o * 32 + k], acc);
        out[(b0 + bb) * 2 + o] = acc;
    }
}

// ---------------------------------------------------------------------------
extern "C" void kernel_launch(void* const* d_in, const int* in_sizes, int n_in,
                              void* d_out, int out_size)
{
    const float* conn  = (const float*)d_in[0];
    const int*   mask  = (const int*)  d_in[1];
    const float* w1_w  = (const float*)d_in[2];
    const float* w1_b  = (const float*)d_in[3];
    const float* w2_w  = (const float*)d_in[4];
    const float* w2_b  = (const float*)d_in[5];
    const float* Wih0  = (const float*)d_in[6];
    const float* Whh0  = (const float*)d_in[7];
    const float* bih0  = (const float*)d_in[8];
    const float* bhh0  = (const float*)d_in[9];
    const float* Wih1  = (const float*)d_in[10];
    const float* Whh1  = (const float*)d_in[11];
    const float* bih1  = (const float*)d_in[12];
    const float* bhh1  = (const float*)d_in[13];
    const float* fc1_w = (const float*)d_in[14];
    const float* fc1_b = (const float*)d_in[15];
    const float* fc2_w = (const float*)d_in[16];
    const float* fc2_b = (const float*)d_in[17];
    float* out = (float*)d_out;

    (void)cudaFuncSetAttribute((const void*)encoder_kernel,
                               cudaFuncAttributePreferredSharedMemoryCarveout, 100);

    encoder_kernel<<<888, 64>>>(conn, mask, w1_w, w1_b, w2_w, w2_b);
    xg_kernel<<<BT / 64, 128>>>(Wih0, bih0, bhh0);
    lstm_kernel<<<Bb / 2, 384>>>(mask, Whh0, Wih1, Whh1, bih1, bhh1,
                                 fc1_w, fc1_b, fc2_w, fc2_b, out);
}